// round 2
// baseline (speedup 1.0000x reference)
#include <cuda_runtime.h>
#include <cuda_bf16.h>
#include <math.h>

#define NBINS   256
#define WARPS   12
#define BLOCK   (WARPS * 32)          // 384 threads
#define GRID    148                   // one CTA per SM, one wave
#define REG_HW  (NBINS * 32)          // 8192 halfwords per warp region
#define DYN_SMEM (WARPS * REG_HW * 2) // 196608 bytes

__device__ unsigned int g_partials[GRID * NBINS];

__global__ __launch_bounds__(BLOCK, 1)
void hist_kernel(const float* __restrict__ x, int n) {
    extern __shared__ unsigned short sh16[];
    __shared__ unsigned int s_final[NBINS];

    const int tid  = threadIdx.x;
    const int lane = tid & 31;
    const int warp = tid >> 5;

    // zero: 192KB as uint4 (12288 uint4) + final
    uint4 z = make_uint4(0u, 0u, 0u, 0u);
    #pragma unroll
    for (int i = tid; i < (WARPS * REG_HW * 2) / 16; i += BLOCK)
        ((uint4*)sh16)[i] = z;
    if (tid < NBINS) s_final[tid] = 0u;
    __syncthreads();

    unsigned short* reg = sh16 + warp * REG_HW;
    const float w = 0.99609375f;      // 255/256, exact fp32

    const int n4 = n >> 2;
    const float4* __restrict__ x4 = (const float4*)x;
    const int stride = GRID * BLOCK;
    const int gid = blockIdx.x * BLOCK + tid;

    // main loop: batch 8 LDG.128 for MLP, then bin 32 elements
    for (int base = gid; base < n4; base += 8 * stride) {
        float4 v[8];
        #pragma unroll
        for (int u = 0; u < 8; u++) {
            int i = base + u * stride;
            if (i < n4) v[u] = x4[i];
        }
        #pragma unroll
        for (int u = 0; u < 8; u++) {
            int i = base + u * stride;
            if (i < n4) {
                #pragma unroll
                for (int k = 0; k < 4; k++) {
                    float f = (k == 0) ? v[u].x : (k == 1) ? v[u].y
                            : (k == 2) ? v[u].z : v[u].w;
                    if (f >= 0.0f && f <= 255.0f) {
                        int idx = (int)floorf(__fdiv_rn(f, w));
                        idx = min(idx, NBINS - 1);
                        reg[idx * 32 + lane] += (unsigned short)1;
                    }
                }
            }
        }
    }

    // scalar tail (n % 4)
    for (int i = (n4 << 2) + gid; i < n; i += stride) {
        float f = x[i];
        if (f >= 0.0f && f <= 255.0f) {
            int idx = (int)floorf(__fdiv_rn(f, w));
            idx = min(idx, NBINS - 1);
            reg[idx * 32 + lane] += (unsigned short)1;
        }
    }

    __syncthreads();

    // per-warp merge of its own region, bank-conflict-free:
    //   lane l handles bins b = g*32 + (l&15)*2 + (l>>4); reads row b as 16
    //   uint32 words with column rotation (l&15)+j.
    //   bank = 16*(b&1) + wordcol = 16*(l>>4) + ((l&15)+j)&15 -> 32 distinct.
    const unsigned int* reg32 = (const unsigned int*)(sh16 + warp * REG_HW);
    const int ll   = lane & 15;
    const int half = lane >> 4;
    const int bin_local = ll * 2 + half;
    #pragma unroll
    for (int g = 0; g < 8; g++) {
        int b = g * 32 + bin_local;
        unsigned int s = 0;
        #pragma unroll
        for (int j = 0; j < 16; j++) {
            int c = (ll + j) & 15;
            unsigned int vv = reg32[b * 16 + c];
            s += (vv & 0xFFFFu) + (vv >> 16);
        }
        atomicAdd(&s_final[b], s);    // 12 warps x 256 bins, spread, cheap
    }
    __syncthreads();

    if (tid < NBINS)
        g_partials[blockIdx.x * NBINS + tid] = s_final[tid];
}

__global__ void finalize_kernel(const void* __restrict__ bs_ptr,
                                float* __restrict__ out) {
    __shared__ float s_h0;
    const int b = threadIdx.x;

    // 8 independent accumulators for MLP over the 148 partials
    unsigned int acc[8] = {0,0,0,0,0,0,0,0};
    int k = 0;
    for (; k + 8 <= GRID; k += 8) {
        #pragma unroll
        for (int u = 0; u < 8; u++)
            acc[u] += g_partials[(k + u) * NBINS + b];
    }
    unsigned int s = 0;
    for (; k < GRID; k++) s += g_partials[k * NBINS + b];
    #pragma unroll
    for (int u = 0; u < 8; u++) s += acc[u];

    float h = (float)s;
    if (b == 0) s_h0 = h;
    __syncthreads();

    // sniff batchsize dtype (int32 16 vs float32 16.0)
    int iv = *(const int*)bs_ptr;
    float bs = (iv >= 0 && iv < (1 << 24)) ? (float)iv : *(const float*)bs_ptr;

    out[b]         = h;
    out[NBINS + b] = bs * s_h0;
}

extern "C" void kernel_launch(void* const* d_in, const int* in_sizes, int n_in,
                              void* d_out, int out_size) {
    int img_idx = 0, bs_idx = 1;
    if (n_in >= 2) {
        if (in_sizes[0] >= in_sizes[1]) { img_idx = 0; bs_idx = 1; }
        else                            { img_idx = 1; bs_idx = 0; }
    }
    const float* x = (const float*)d_in[img_idx];
    const void* bs = d_in[bs_idx];
    int n = in_sizes[img_idx];

    static bool attr_set = false;
    if (!attr_set) {
        cudaFuncSetAttribute(hist_kernel,
                             cudaFuncAttributeMaxDynamicSharedMemorySize,
                             DYN_SMEM);
        attr_set = true;
    }

    hist_kernel<<<GRID, BLOCK, DYN_SMEM>>>(x, n);
    finalize_kernel<<<1, NBINS>>>(bs, (float*)d_out);
}

// round 3
// speedup vs baseline: 2.4355x; 2.4355x over previous
#include <cuda_runtime.h>
#include <cuda_bf16.h>
#include <math.h>

#define NBINS   256
#define NCOPIES 8              // one sub-histogram per warp
#define THREADS 256
#define BLOCKS  592            // 4 CTAs/SM * 148 SMs
#define BATCH   4

__device__ unsigned int g_hist[NBINS];   // zero-initialized at module load

__global__ __launch_bounds__(THREADS) void hist_kernel(const float* __restrict__ x, int n) {
    __shared__ unsigned int sh[NCOPIES][NBINS];

    const int tid  = threadIdx.x;
    const int warp = tid >> 5;

    #pragma unroll
    for (int c = 0; c < NCOPIES; c++)
        sh[c][tid] = 0u;
    __syncthreads();

    unsigned int* myhist = sh[warp];
    const float scale = 1.00392156862745097e+00f;   // rn(256/255)

    const int n4 = n >> 2;
    const float4* __restrict__ x4 = (const float4*)x;
    const int stride = BLOCKS * THREADS;
    const int gid = blockIdx.x * THREADS + tid;

    for (int base = gid; base < n4; base += BATCH * stride) {
        float4 v[BATCH];
        #pragma unroll
        for (int u = 0; u < BATCH; u++) {
            int i = base + u * stride;
            if (i < n4) v[u] = x4[i];
        }
        #pragma unroll
        for (int u = 0; u < BATCH; u++) {
            int i = base + u * stride;
            if (i < n4) {
                #pragma unroll
                for (int k = 0; k < 4; k++) {
                    float f = (k == 0) ? v[u].x : (k == 1) ? v[u].y
                            : (k == 2) ? v[u].z : v[u].w;
                    // trunc == floor for f>=0; FMUL+F2I instead of fdiv+floor
                    int idx = (int)(f * scale);
                    idx = min(idx, NBINS - 1);
                    if (f >= 0.0f && f <= 255.0f)
                        atomicAdd(&myhist[idx], 1u);
                }
            }
        }
    }

    // scalar tail (n % 4)
    for (int i = (n4 << 2) + gid; i < n; i += stride) {
        float f = x[i];
        int idx = (int)(f * scale);
        idx = min(idx, NBINS - 1);
        if (f >= 0.0f && f <= 255.0f)
            atomicAdd(&myhist[idx], 1u);
    }

    __syncthreads();

    unsigned int total = 0;
    #pragma unroll
    for (int c = 0; c < NCOPIES; c++)
        total += sh[c][tid];
    if (total) atomicAdd(&g_hist[tid], total);
}

__global__ void finalize_kernel(const void* __restrict__ bs_ptr,
                                float* __restrict__ out) {
    const int b = threadIdx.x;

    unsigned int hv = g_hist[b];
    unsigned int h0 = g_hist[0];        // L2 broadcast

    // batchsize dtype sniff: int32 small value vs float32 bit pattern
    int iv = *(const int*)bs_ptr;
    float bs = (iv >= 0 && iv < (1 << 24)) ? (float)iv : *(const float*)bs_ptr;

    out[b]         = (float)hv;
    out[NBINS + b] = bs * (float)h0;

    __syncthreads();                     // everyone has read g_hist
    g_hist[b] = 0u;                      // reset for next graph replay
}

extern "C" void kernel_launch(void* const* d_in, const int* in_sizes, int n_in,
                              void* d_out, int out_size) {
    int img_idx = 0, bs_idx = 1;
    if (n_in >= 2) {
        if (in_sizes[0] >= in_sizes[1]) { img_idx = 0; bs_idx = 1; }
        else                            { img_idx = 1; bs_idx = 0; }
    }
    const float* x = (const float*)d_in[img_idx];
    const void* bs = d_in[bs_idx];
    int n = in_sizes[img_idx];

    hist_kernel<<<BLOCKS, THREADS>>>(x, n);
    finalize_kernel<<<1, NBINS>>>(bs, (float*)d_out);
}